// round 15
// baseline (speedup 1.0000x reference)
#include <cuda_runtime.h>
#include <math.h>

#define Bv    8
#define Tv    4096
#define Dv    1024
#define Hv    8
#define Pv    1024
#define OUTv  1024
#define NWIN  128
#define WPB   4               // windows per block
#define WG    (NWIN/WPB)      // 32 window-groups
#define TSPAN 160             // tokens spanned per block (32*WPB + 32)
#define NCHUNK 5              // 20 tokens per warp / 4

// ---------------- scratch (static device globals; no allocation) ----------------
__device__ __align__(16) float g_qk[Hv*Dv];             // 32 KB (pre-scaled by 1/sqrt(128))
__device__ __align__(16) float g_ypart[WG*Bv*Hv*Dv];    // 8 MB   [wg][b][h][d]
__device__ __align__(16) float g_agg[Bv*Pv];            // 32 KB

// ---------------- helpers ----------------
__device__ __forceinline__ float wredsum(float v){
#pragma unroll
    for (int o = 16; o; o >>= 1) v += __shfl_xor_sync(0xffffffffu, v, o);
    return v;
}
__device__ __forceinline__ float wredmax(float v){
#pragma unroll
    for (int o = 16; o; o >>= 1) v = fmaxf(v, __shfl_xor_sync(0xffffffffu, v, o));
    return v;
}
__device__ __forceinline__ unsigned long long fma2(unsigned long long a,
                                                   unsigned long long b,
                                                   unsigned long long c){
    unsigned long long d;
    asm("fma.rn.f32x2 %0, %1, %2, %3;" : "=l"(d) : "l"(a), "l"(b), "l"(c));
    return d;
}
__device__ __forceinline__ unsigned long long add2(unsigned long long a,
                                                   unsigned long long b){
    unsigned long long d;
    asm("add.rn.f32x2 %0, %1, %2;" : "=l"(d) : "l"(a), "l"(b));
    return d;
}
__device__ __forceinline__ float2 unpack2(unsigned long long v){
    float2 r; asm("mov.b64 {%0, %1}, %2;" : "=f"(r.x), "=f"(r.y) : "l"(v)); return r;
}
__device__ __forceinline__ unsigned long long pack2(float lo, float hi){
    unsigned long long v; asm("mov.b64 %0, {%1, %2};" : "=l"(v) : "f"(lo), "f"(hi)); return v;
}
__device__ __forceinline__ unsigned long long wredsum2(unsigned long long v){
#pragma unroll
    for (int o = 16; o; o >>= 1){
        unsigned long long t = __shfl_xor_sync(0xffffffffu, v, o);
        v = add2(v, t);
    }
    return v;
}

// ---------------- 1) qk[h,d] = (1/sqrt(128)) * sum_hd w_kv[d, h*128+hd] * query[h,hd] ----------------
__global__ void k_qk(const float* __restrict__ w_kv, const float* __restrict__ query){
    int g    = blockIdx.x * 8 + (threadIdx.x >> 5);
    int lane = threadIdx.x & 31;
    int h = g >> 10, d = g & 1023;
    float4 wv = *(const float4*)(w_kv + (size_t)d*2048 + h*128 + lane*4);
    float4 qv = *(const float4*)(query + h*128 + lane*4);
    float s = wv.x*qv.x + wv.y*qv.y + wv.z*qv.z + wv.w*qv.w;
    s = wredsum(s);
    if (lane == 0) g_qk[h*Dv + d] = s * 0.08838834764831845f;
}

// ---------------- 2) fused logits + windowed softmax + weighted V-sum partials ----------------
// FROZEN: proven at 90.2/91.4/92.0/92.9us. TPC=4, qk in smem, wredsum2 on packed
// accumulators, launch_bounds(256,2). Any perturbation of phase A spills.
__global__ void __launch_bounds__(256, 2) k_fused(const float* __restrict__ x){
    __shared__ float qs[Hv*Dv];                         // 32 KB
    __shared__ float lg[Hv][TSPAN+4];                   // 5.1 KB logits (padded)
    __shared__ unsigned long long cw2[Hv][TSPAN];       // 10 KB (w,w) pairs

    int tid  = threadIdx.x;
    int wg   = blockIdx.x;
    int b    = blockIdx.y;
    int tbase = wg * (32*WPB);

#pragma unroll
    for (int i = 0; i < 8; i++)
        ((float4*)qs)[tid + i*256] = ((const float4*)g_qk)[tid + i*256];
    for (int i = tid; i < Hv*TSPAN; i += 256) ((unsigned long long*)cw2)[i] = 0ull;
    __syncthreads();

    int warp = tid >> 5, lane = tid & 31;

    // ---- phase A: logits, 20 tokens per warp, 5 chunks of 4 ----
#pragma unroll 1
    for (int c = 0; c < NCHUNK; c++){
        int tokl = warp*(4*NCHUNK) + c*4;
        unsigned long long acc[4][8];
#pragma unroll
        for (int j = 0; j < 4; j++)
#pragma unroll
            for (int h = 0; h < 8; h++) acc[j][h] = 0ull;

        const float* rp[4];
#pragma unroll
        for (int j = 0; j < 4; j++){
            int t = tbase + tokl + j;
            t = t < Tv ? t : Tv - 1;                    // clamp OOB rows (masked later)
            rp[j] = x + ((size_t)b*Tv + t)*Dv + lane*4;
        }
#pragma unroll
        for (int i = 0; i < 8; i++){
            ulonglong2 xr[4];
#pragma unroll
            for (int j = 0; j < 4; j++)
                xr[j] = *(const ulonglong2*)(rp[j] + i*128);
#pragma unroll
            for (int h = 0; h < 8; h++){
                ulonglong2 q = *(const ulonglong2*)(qs + h*Dv + i*128 + lane*4);
#pragma unroll
                for (int j = 0; j < 4; j++){
                    acc[j][h] = fma2(xr[j].x, q.x, acc[j][h]);
                    acc[j][h] = fma2(xr[j].y, q.y, acc[j][h]);
                }
            }
        }
        float my = 0.f;
#pragma unroll
        for (int h = 0; h < 8; h++)
#pragma unroll
            for (int j = 0; j < 4; j++){
                unsigned long long r = wredsum2(acc[j][h]);
                float2 p = unpack2(r);
                float s = p.x + p.y;
                if (lane == h*4 + j) my = s;
            }
        int h = lane >> 2, j = lane & 3;
        int tok = tokl + j;
        lg[h][tok] = (tbase + tok < Tv) ? my : -3.0e38f;
    }
    __syncthreads();

    // ---- phase B: WPB windows' softmax per head (warp == head), pair RMW ----
#pragma unroll
    for (int wi = 0; wi < WPB; wi++){
        int t0l = wi*32;
        float l0 = lg[warp][t0l + lane];
        float l1 = lg[warp][t0l + lane + 32];
        float m  = wredmax(fmaxf(l0, l1));
        float e0 = __expf(l0 - m);
        float e1 = __expf(l1 - m);
        float z  = wredsum(e0 + e1);
        float inv = (1.0f/128.0f) / z;
        float w0 = e0 * inv, w1 = e1 * inv;
        cw2[warp][t0l + lane]      = add2(cw2[warp][t0l + lane],      pack2(w0, w0));
        cw2[warp][t0l + lane + 32] = add2(cw2[warp][t0l + lane + 32], pack2(w1, w1));
    }
    __syncthreads();

    // ---- phase C: y partial, thread owns 4 d channels; x re-read hits L2 ----
    int tmax = TSPAN < (Tv - tbase) ? TSPAN : (Tv - tbase);
    const float* xb = x + ((size_t)b*Tv + tbase)*Dv + tid*4;
    unsigned long long acc[8][2];
#pragma unroll
    for (int h = 0; h < 8; h++){ acc[h][0] = 0ull; acc[h][1] = 0ull; }

#pragma unroll 4
    for (int tt = 0; tt < tmax; tt++){
        ulonglong2 xv = *(const ulonglong2*)(xb + (size_t)tt*Dv);
#pragma unroll
        for (int h = 0; h < 8; h++){
            unsigned long long w2 = cw2[h][tt];
            acc[h][0] = fma2(xv.x, w2, acc[h][0]);
            acc[h][1] = fma2(xv.y, w2, acc[h][1]);
        }
    }
    int dbase = tid*4;
#pragma unroll
    for (int h = 0; h < 8; h++){
        float2 a = unpack2(acc[h][0]);
        float2 c = unpack2(acc[h][1]);
        float4 o = make_float4(a.x, a.y, c.x, c.y);
        *(float4*)(g_ypart + ((((size_t)wg*Bv + b)*Hv + h)*Dv) + dbase) = o;
    }
}

// ---------------- 3) fused y-reduce + V-proj, FINAL agg (proven) ----------------
// grid (h=8, b=8, pseg=4) = 256 blocks, block 256 (8 warps).
__global__ void k_agg(const float* __restrict__ w_kv){
    __shared__ float ys[Dv];                            // 4 KB
    __shared__ float part[8*32];                        // 1 KB
    int tid  = threadIdx.x;
    int h    = blockIdx.x;
    int b    = blockIdx.y;
    int ps   = blockIdx.z;
    int warp = tid >> 5, lane = tid & 31;

    // step 1: y[d] = sum_wg ypart[wg][b][h][d]; thread owns d = tid*4..+3 (L2-hot)
    int d0 = tid*4;
    const float* yp = g_ypart + (((size_t)b*Hv + h)*Dv) + d0;
    float4 y4 = make_float4(0.f,0.f,0.f,0.f);
#pragma unroll 8
    for (int wgi = 0; wgi < WG; wgi++){
        float4 v = *(const float4*)(yp + (size_t)wgi*(Bv*Hv*Dv));
        y4.x += v.x; y4.y += v.y; y4.z += v.z; y4.w += v.w;
    }
    *(float4*)(ys + d0) = y4;
    __syncthreads();

    // step 2: warp w covers d in [w*128,(w+1)*128); lane owns p = h*128+ps*32+lane
    int p = h*128 + ps*32 + lane;
    const float* wvp = w_kv + 1024 + p;
    float acc = 0.f;
#pragma unroll 8
    for (int k = 0; k < 128; k++){
        int d = warp*128 + k;
        acc += ys[d] * wvp[(size_t)d*2048];             // coalesced 128B line per warp
    }
    part[warp*32 + lane] = acc;
    __syncthreads();

    // step 3: reduce 8 warp partials, write final
    if (tid < 32){
        float s = 0.f;
#pragma unroll
        for (int w = 0; w < 8; w++) s += part[w*32 + tid];
        g_agg[(size_t)b*Pv + h*128 + ps*32 + tid] = s;
    }
}

// ---------------- 4) out[b,o] = bias[o] + sum_p w_out[o,p]*agg[b,p] ----------------
// 256 blocks x 128 thr (grid was SM-coverage-limited at 128); front-loaded w_out
// regs (MLP=8); g_agg (32 KB, block-shared) read direct via __ldg -> L1-hot.
__global__ void k_out(const float* __restrict__ w_out, const float* __restrict__ w_b,
                      float* __restrict__ out){
    int tid  = threadIdx.x;
    int warp = tid >> 5, lane = tid & 31;
    int o = blockIdx.x*4 + warp;

    float4 w4[8];                                       // issue DRAM loads first
#pragma unroll
    for (int i = 0; i < 8; i++)
        w4[i] = *(const float4*)(w_out + (size_t)o*Pv + i*128 + lane*4);

    float acc[8];
#pragma unroll
    for (int b = 0; b < 8; b++) acc[b] = 0.f;
#pragma unroll
    for (int i = 0; i < 8; i++){
#pragma unroll
        for (int b = 0; b < 8; b++){
            float4 a4 = __ldg((const float4*)(g_agg + (size_t)b*Pv + i*128 + lane*4));
            acc[b] += w4[i].x*a4.x + w4[i].y*a4.y + w4[i].z*a4.z + w4[i].w*a4.w;
        }
    }
#pragma unroll
    for (int b = 0; b < 8; b++) acc[b] = wredsum(acc[b]);
    if (lane == 0){
        float bias = w_b[o];
#pragma unroll
        for (int b = 0; b < 8; b++) out[(size_t)b*OUTv + o] = acc[b] + bias;
    }
}

// ---------------- launch ----------------
extern "C" void kernel_launch(void* const* d_in, const int* in_sizes, int n_in,
                              void* d_out, int out_size){
    const float* x     = (const float*)d_in[0];
    const float* w_kv  = (const float*)d_in[1];
    const float* query = (const float*)d_in[2];
    const float* w_out = (const float*)d_in[3];
    const float* w_b   = (const float*)d_in[4];
    float* out = (float*)d_out;

    k_qk    <<<1024, 256>>>(w_kv, query);
    dim3 gf(WG, Bv);
    k_fused <<<gf, 256>>>(x);
    dim3 ga(Hv, Bv, 4);
    k_agg   <<<ga, 256>>>(w_kv);
    k_out   <<<256, 128>>>(w_out, w_b, out);
}

// round 16
// speedup vs baseline: 1.0643x; 1.0643x over previous
#include <cuda_runtime.h>
#include <math.h>

#define Bv    8
#define Tv    4096
#define Dv    1024
#define Hv    8
#define Pv    1024
#define OUTv  1024
#define NWIN  128
#define WPB   4               // windows per block
#define WG    (NWIN/WPB)      // 32 window-groups
#define TSPAN 160             // tokens spanned per block (32*WPB + 32)
#define NCHUNK 5              // 20 tokens per warp / 4

// ---------------- scratch (static device globals; no allocation) ----------------
__device__ __align__(16) float g_qk[Hv*Dv];             // 32 KB (pre-scaled by 1/sqrt(128))
__device__ __align__(16) float g_ypart[WG*Bv*Hv*Dv];    // 8 MB   [wg][b][h][d]
__device__ __align__(16) float g_aggpart[32*Bv*Pv];     // 1 MB   [dseg][b][p]
__device__ __align__(16) float g_agg[Bv*Pv];            // 32 KB

// ---------------- helpers ----------------
__device__ __forceinline__ float wredsum(float v){
#pragma unroll
    for (int o = 16; o; o >>= 1) v += __shfl_xor_sync(0xffffffffu, v, o);
    return v;
}
__device__ __forceinline__ float wredmax(float v){
#pragma unroll
    for (int o = 16; o; o >>= 1) v = fmaxf(v, __shfl_xor_sync(0xffffffffu, v, o));
    return v;
}
__device__ __forceinline__ unsigned long long fma2(unsigned long long a,
                                                   unsigned long long b,
                                                   unsigned long long c){
    unsigned long long d;
    asm("fma.rn.f32x2 %0, %1, %2, %3;" : "=l"(d) : "l"(a), "l"(b), "l"(c));
    return d;
}
__device__ __forceinline__ unsigned long long add2(unsigned long long a,
                                                   unsigned long long b){
    unsigned long long d;
    asm("add.rn.f32x2 %0, %1, %2;" : "=l"(d) : "l"(a), "l"(b));
    return d;
}
__device__ __forceinline__ float2 unpack2(unsigned long long v){
    float2 r; asm("mov.b64 {%0, %1}, %2;" : "=f"(r.x), "=f"(r.y) : "l"(v)); return r;
}
__device__ __forceinline__ unsigned long long pack2(float lo, float hi){
    unsigned long long v; asm("mov.b64 %0, {%1, %2};" : "=l"(v) : "f"(lo), "f"(hi)); return v;
}
__device__ __forceinline__ unsigned long long wredsum2(unsigned long long v){
#pragma unroll
    for (int o = 16; o; o >>= 1){
        unsigned long long t = __shfl_xor_sync(0xffffffffu, v, o);
        v = add2(v, t);
    }
    return v;
}

// ---------------- 1) qk[h,d] = (1/sqrt(128)) * sum_hd w_kv[d, h*128+hd] * query[h,hd] ----------------
__global__ void k_qk(const float* __restrict__ w_kv, const float* __restrict__ query){
    int g    = blockIdx.x * 8 + (threadIdx.x >> 5);
    int lane = threadIdx.x & 31;
    int h = g >> 10, d = g & 1023;
    float4 wv = *(const float4*)(w_kv + (size_t)d*2048 + h*128 + lane*4);
    float4 qv = *(const float4*)(query + h*128 + lane*4);
    float s = wv.x*qv.x + wv.y*qv.y + wv.z*qv.z + wv.w*qv.w;
    s = wredsum(s);
    if (lane == 0) g_qk[h*Dv + d] = s * 0.08838834764831845f;
}

// ---------------- 2) fused logits + windowed softmax + weighted V-sum partials ----------------
// FROZEN: proven at 90.2/91.4/92.0/92.9us. TPC=4, qk in smem, wredsum2 on packed
// accumulators, launch_bounds(256,2). Any perturbation of phase A spills.
__global__ void __launch_bounds__(256, 2) k_fused(const float* __restrict__ x){
    __shared__ float qs[Hv*Dv];                         // 32 KB
    __shared__ float lg[Hv][TSPAN+4];                   // 5.1 KB logits (padded)
    __shared__ unsigned long long cw2[Hv][TSPAN];       // 10 KB (w,w) pairs

    int tid  = threadIdx.x;
    int wg   = blockIdx.x;
    int b    = blockIdx.y;
    int tbase = wg * (32*WPB);

#pragma unroll
    for (int i = 0; i < 8; i++)
        ((float4*)qs)[tid + i*256] = ((const float4*)g_qk)[tid + i*256];
    for (int i = tid; i < Hv*TSPAN; i += 256) ((unsigned long long*)cw2)[i] = 0ull;
    __syncthreads();

    int warp = tid >> 5, lane = tid & 31;

    // ---- phase A: logits, 20 tokens per warp, 5 chunks of 4 ----
#pragma unroll 1
    for (int c = 0; c < NCHUNK; c++){
        int tokl = warp*(4*NCHUNK) + c*4;
        unsigned long long acc[4][8];
#pragma unroll
        for (int j = 0; j < 4; j++)
#pragma unroll
            for (int h = 0; h < 8; h++) acc[j][h] = 0ull;

        const float* rp[4];
#pragma unroll
        for (int j = 0; j < 4; j++){
            int t = tbase + tokl + j;
            t = t < Tv ? t : Tv - 1;                    // clamp OOB rows (masked later)
            rp[j] = x + ((size_t)b*Tv + t)*Dv + lane*4;
        }
#pragma unroll
        for (int i = 0; i < 8; i++){
            ulonglong2 xr[4];
#pragma unroll
            for (int j = 0; j < 4; j++)
                xr[j] = *(const ulonglong2*)(rp[j] + i*128);
#pragma unroll
            for (int h = 0; h < 8; h++){
                ulonglong2 q = *(const ulonglong2*)(qs + h*Dv + i*128 + lane*4);
#pragma unroll
                for (int j = 0; j < 4; j++){
                    acc[j][h] = fma2(xr[j].x, q.x, acc[j][h]);
                    acc[j][h] = fma2(xr[j].y, q.y, acc[j][h]);
                }
            }
        }
        float my = 0.f;
#pragma unroll
        for (int h = 0; h < 8; h++)
#pragma unroll
            for (int j = 0; j < 4; j++){
                unsigned long long r = wredsum2(acc[j][h]);
                float2 p = unpack2(r);
                float s = p.x + p.y;
                if (lane == h*4 + j) my = s;
            }
        int h = lane >> 2, j = lane & 3;
        int tok = tokl + j;
        lg[h][tok] = (tbase + tok < Tv) ? my : -3.0e38f;
    }
    __syncthreads();

    // ---- phase B: WPB windows' softmax per head (warp == head), pair RMW ----
#pragma unroll
    for (int wi = 0; wi < WPB; wi++){
        int t0l = wi*32;
        float l0 = lg[warp][t0l + lane];
        float l1 = lg[warp][t0l + lane + 32];
        float m  = wredmax(fmaxf(l0, l1));
        float e0 = __expf(l0 - m);
        float e1 = __expf(l1 - m);
        float z  = wredsum(e0 + e1);
        float inv = (1.0f/128.0f) / z;
        float w0 = e0 * inv, w1 = e1 * inv;
        cw2[warp][t0l + lane]      = add2(cw2[warp][t0l + lane],      pack2(w0, w0));
        cw2[warp][t0l + lane + 32] = add2(cw2[warp][t0l + lane + 32], pack2(w1, w1));
    }
    __syncthreads();

    // ---- phase C: y partial, thread owns 4 d channels; x re-read hits L2 ----
    int tmax = TSPAN < (Tv - tbase) ? TSPAN : (Tv - tbase);
    const float* xb = x + ((size_t)b*Tv + tbase)*Dv + tid*4;
    unsigned long long acc[8][2];
#pragma unroll
    for (int h = 0; h < 8; h++){ acc[h][0] = 0ull; acc[h][1] = 0ull; }

#pragma unroll 4
    for (int tt = 0; tt < tmax; tt++){
        ulonglong2 xv = *(const ulonglong2*)(xb + (size_t)tt*Dv);
#pragma unroll
        for (int h = 0; h < 8; h++){
            unsigned long long w2 = cw2[h][tt];
            acc[h][0] = fma2(xv.x, w2, acc[h][0]);
            acc[h][1] = fma2(xv.y, w2, acc[h][1]);
        }
    }
    int dbase = tid*4;
#pragma unroll
    for (int h = 0; h < 8; h++){
        float2 a = unpack2(acc[h][0]);
        float2 c = unpack2(acc[h][1]);
        float4 o = make_float4(a.x, a.y, c.x, c.y);
        *(float4*)(g_ypart + ((((size_t)wg*Bv + b)*Hv + h)*Dv) + dbase) = o;
    }
}

// ---------------- 3) y-reduce + agg partials (R10-measured shape, 92.0us run) ----------------
// grid (dseg=32, h=8, bq=2) = 512 blocks, block 128 (warp = batch, lanes = d/p).
__global__ void k_agg(const float* __restrict__ w_kv){
    int tid  = threadIdx.x;
    int dseg = blockIdx.x;
    int h    = blockIdx.y;
    int b    = blockIdx.z*4 + (tid >> 5);
    int lane = tid & 31;

    // reduce ypart over window-groups for this (b,h,dseg*32+lane)
    const float* yp = g_ypart + (((size_t)b*Hv + h)*Dv) + dseg*32 + lane;
    float yv = 0.f;
#pragma unroll 8
    for (int wgi = 0; wgi < WG; wgi++)
        yv += yp[(size_t)wgi*(Bv*Hv*Dv)];

    int p = h*128 + lane*4;
    float4 acc = make_float4(0.f,0.f,0.f,0.f);
#pragma unroll
    for (int dd = 0; dd < 32; dd++){
        float yd = __shfl_sync(0xffffffffu, yv, dd);
        int d = dseg*32 + dd;
        float4 wv = *(const float4*)(w_kv + (size_t)d*2048 + 1024 + p);
        acc.x += yd*wv.x; acc.y += yd*wv.y;
        acc.z += yd*wv.z; acc.w += yd*wv.w;
    }
    *(float4*)(g_aggpart + ((size_t)dseg*Bv + b)*Pv + p) = acc;
}

// ---------------- 4) reduce agg partials (measured 5.0us at 64x128) ----------------
__global__ void k_aggred(){
    int i = blockIdx.x*blockDim.x + threadIdx.x;        // 8192
    float s = 0.f;
#pragma unroll
    for (int seg = 0; seg < 32; seg++) s += g_aggpart[(size_t)seg*(Bv*Pv) + i];
    g_agg[i] = s;
}

// ---------------- 5) out[b,o] = bias[o] + sum_p w_out[o,p]*agg[b,p] ----------------
// R13/R14-measured best (8.7us): grid 128x256, smem-staged aggs + front-loaded
// w_out regs overlapping the staging barrier.
__global__ void k_out(const float* __restrict__ w_out, const float* __restrict__ w_b,
                      float* __restrict__ out){
    __shared__ float aggs[Bv*Pv];                       // 32 KB
    int tid  = threadIdx.x;
    int warp = tid >> 5, lane = tid & 31;
    int o = blockIdx.x*8 + warp;

    float4 w4[8];                                       // issue DRAM loads first
#pragma unroll
    for (int i = 0; i < 8; i++)
        w4[i] = *(const float4*)(w_out + (size_t)o*Pv + i*128 + lane*4);

#pragma unroll
    for (int i = 0; i < 8; i++)
        ((float4*)aggs)[tid + i*256] = ((const float4*)g_agg)[tid + i*256];
    __syncthreads();

    float acc[8];
#pragma unroll
    for (int b = 0; b < 8; b++) acc[b] = 0.f;
#pragma unroll
    for (int i = 0; i < 8; i++){
#pragma unroll
        for (int b = 0; b < 8; b++){
            float4 a4 = *(const float4*)(aggs + b*Pv + i*128 + lane*4);
            acc[b] += w4[i].x*a4.x + w4[i].y*a4.y + w4[i].z*a4.z + w4[i].w*a4.w;
        }
    }
#pragma unroll
    for (int b = 0; b < 8; b++) acc[b] = wredsum(acc[b]);
    if (lane == 0){
        float bias = w_b[o];
#pragma unroll
        for (int b = 0; b < 8; b++) out[(size_t)b*OUTv + o] = acc[b] + bias;
    }
}

// ---------------- launch ----------------
extern "C" void kernel_launch(void* const* d_in, const int* in_sizes, int n_in,
                              void* d_out, int out_size){
    const float* x     = (const float*)d_in[0];
    const float* w_kv  = (const float*)d_in[1];
    const float* query = (const float*)d_in[2];
    const float* w_out = (const float*)d_in[3];
    const float* w_b   = (const float*)d_in[4];
    float* out = (float*)d_out;

    k_qk    <<<1024, 256>>>(w_kv, query);
    dim3 gf(WG, Bv);
    k_fused <<<gf, 256>>>(x);
    dim3 ga(32, Hv, 2);
    k_agg   <<<ga, 128>>>(w_kv);
    k_aggred<<<64, 128>>>();
    k_out   <<<128, 256>>>(w_out, w_b, out);
}